// round 16
// baseline (speedup 1.0000x reference)
#include <cuda_runtime.h>
#include <cuda_fp16.h>
#include <cstdint>

#define NB   4
#define SEQ  2048
#define DM   1024
#define MTOT (NB*SEQ)          // 8192
#define NW   (DM*DM)

#define BM 128
#define BN 128
#define BK 64
#define STAGES 3
#define TILE_BYTES (BM*BK*2)                // 16384 B per operand tile (128B rows)
#define SMEM_BYTES (STAGES*2*TILE_BYTES)    // 98304 B -> 2 CTAs/SM (192KB)

// ------------------------- scratch (__device__ globals; no allocs) ----------
__device__ __half g_X16[MTOT*DM];
__device__ __half g_Wq16[NW];
__device__ __half g_Wk16[NW];
__device__ __half g_Wv16[NW];
__device__ __half g_Q16[MTOT*DM];
__device__ __half g_K16[MTOT*DM];
__device__ __half g_V16[DM*MTOT];            // Vt: [DM, MTOT]
__device__ float  g_S[(size_t)MTOT*SEQ];
__device__ __half g_P16[(size_t)MTOT*SEQ];

// ------------------------- PTX helpers -------------------------------------
__device__ __forceinline__ void cp16(void* s, const void* g) {
    uint32_t sa = (uint32_t)__cvta_generic_to_shared(s);
    asm volatile("cp.async.cg.shared.global [%0], [%1], 16;\n" :: "r"(sa), "l"(g));
}
__device__ __forceinline__ void ldsm4(uint32_t* r, const void* p) {
    uint32_t a = (uint32_t)__cvta_generic_to_shared(p);
    asm volatile("ldmatrix.sync.aligned.m8n8.x4.shared.b16 {%0,%1,%2,%3}, [%4];\n"
                 : "=r"(r[0]), "=r"(r[1]), "=r"(r[2]), "=r"(r[3]) : "r"(a));
}
__device__ __forceinline__ void mma_f16(float* c, const uint32_t* a, const uint32_t* b) {
    asm volatile("mma.sync.aligned.m16n8k16.row.col.f32.f16.f16.f32 "
                 "{%0,%1,%2,%3}, {%4,%5,%6,%7}, {%8,%9}, {%0,%1,%2,%3};\n"
                 : "+f"(c[0]), "+f"(c[1]), "+f"(c[2]), "+f"(c[3])
                 : "r"(a[0]), "r"(a[1]), "r"(a[2]), "r"(a[3]), "r"(b[0]), "r"(b[1]));
}
// 128B rows, 8x16B chunks; chunk' = ch ^ (row&7).
__device__ __forceinline__ int smem_off(int row, int ch) {
    return (row << 7) + (((ch ^ (row & 7)) & 7) << 4);
}

// ------------------------- fp16 GEMM core: 4 warps, 64x64 per warp ----------
// D[m][n] = scale * sum_k A[m][k]*B[n][k]  (both K-major fp16)
// OUT 0: fp16 output    OUT 1: fp32 * scale
template<int OUT>
__device__ __forceinline__ void gemm_core(
    const __half* __restrict__ A, int lda,
    const __half* __restrict__ B, int ldb,
    float* __restrict__ Cf, __half* __restrict__ C16, int ldc,
    int tm, int tn, int kIters, float scale, char* smem)
{
    char* sA = smem;
    char* sB = smem + STAGES * TILE_BYTES;

    const int tid  = threadIdx.x;
    const int lane = tid & 31;
    const int warp = tid >> 5;    // 0..3
    const int wm   = warp >> 1;   // 0..1 (64 rows)
    const int wn   = warp & 1;    // 0..1 (64 cols)

    auto load_stage = [&](int st, int kOff) {
        char* dA = sA + st * TILE_BYTES;
        char* dB = sB + st * TILE_BYTES;
#pragma unroll
        for (int i = 0; i < 8; i++) {
            int idx = tid + (i << 7);
            int row = idx >> 3, ch = idx & 7;
            int so = smem_off(row, ch);
            cp16(dA + so, A + (size_t)(tm + row) * lda + kOff + (ch << 3));
            cp16(dB + so, B + (size_t)(tn + row) * ldb + kOff + (ch << 3));
        }
    };

    // fragment loader for one k16 step
    auto load_frags = [&](const char* cA, const char* cB, int ks,
                          uint32_t (*ah)[4], uint32_t (*bh)[4]) {
#pragma unroll
        for (int mi = 0; mi < 4; mi++) {
            int r  = wm * 64 + mi * 16 + (lane & 15);
            int ch = ks * 2 + (lane >> 4);
            ldsm4(ah[mi], cA + smem_off(r, ch));
        }
#pragma unroll
        for (int pr = 0; pr < 4; pr++) {
            int r  = wn * 64 + pr * 16 + (lane & 7) + (((lane >> 4) & 1) << 3);
            int ch = ks * 2 + ((lane >> 3) & 1);
            ldsm4(bh[pr], cB + smem_off(r, ch));
        }
    };

    // prologue: prefetch depth 2
#pragma unroll
    for (int s = 0; s < STAGES - 1; s++) {
        if (s < kIters) load_stage(s, s * BK);
        asm volatile("cp.async.commit_group;\n" ::);
    }

    float acc[4][8][4];
#pragma unroll
    for (int a = 0; a < 4; a++)
#pragma unroll
        for (int b = 0; b < 8; b++)
#pragma unroll
            for (int c = 0; c < 4; c++) acc[a][b][c] = 0.f;

    for (int kb = 0; kb < kIters; kb++) {
        asm volatile("cp.async.wait_group 1;\n" ::);   // stage kb resident
        __syncthreads();
        int nk = kb + STAGES - 1;
        if (nk < kIters) load_stage(nk % STAGES, nk * BK);
        asm volatile("cp.async.commit_group;\n" ::);

        int st = kb % STAGES;
        const char* cA = sA + st * TILE_BYTES;
        const char* cB = sB + st * TILE_BYTES;

        // double-buffered fragments: load ks+1 while computing ks
        uint32_t ah[2][4][4], bh[2][4][4];
        load_frags(cA, cB, 0, ah[0], bh[0]);
#pragma unroll
        for (int ks = 0; ks < 4; ks++) {
            if (ks < 3) load_frags(cA, cB, ks + 1, ah[(ks + 1) & 1], bh[(ks + 1) & 1]);
            const int cur = ks & 1;
#pragma unroll
            for (int mi = 0; mi < 4; mi++)
#pragma unroll
                for (int pr = 0; pr < 4; pr++) {
                    mma_f16(acc[mi][pr * 2 + 0], ah[cur][mi], bh[cur][pr] + 0);
                    mma_f16(acc[mi][pr * 2 + 1], ah[cur][mi], bh[cur][pr] + 2);
                }
        }
    }

    __syncthreads();

    const int g  = lane >> 2;
    const int tq = lane & 3;
#pragma unroll
    for (int mi = 0; mi < 4; mi++) {
#pragma unroll
        for (int nj = 0; nj < 8; nj++) {
            const float* c = acc[mi][nj];
            int c0 = tn + wn * 64 + nj * 8 + tq * 2;
#pragma unroll
            for (int h = 0; h < 2; h++) {
                int r = tm + wm * 64 + mi * 16 + g + h * 8;
                if (OUT == 0) {
                    __half2 hv;
                    hv.x = __float2half_rn(c[h * 2 + 0]);
                    hv.y = __float2half_rn(c[h * 2 + 1]);
                    *(__half2*)&C16[(size_t)r * ldc + c0] = hv;
                } else {
                    float2 o;
                    o.x = c[h * 2 + 0] * scale;
                    o.y = c[h * 2 + 1] * scale;
                    *(float2*)&Cf[(size_t)r * ldc + c0] = o;
                }
            }
        }
    }
}

// ------------------------- GEMM kernels -------------------------------------
// Merged projections: z=0 Q, z=1 K, z=2 Vt (role-swapped tiles)
__global__ void __launch_bounds__(128, 2) proj_k()
{
    extern __shared__ char smem[];
    int z = blockIdx.z;
    if (z == 0) {
        gemm_core<0>(g_X16, DM, g_Wq16, DM, nullptr, g_Q16, DM,
                     blockIdx.y * BM, blockIdx.x * BN, DM / BK, 1.f, smem);
    } else if (z == 1) {
        gemm_core<0>(g_X16, DM, g_Wk16, DM, nullptr, g_K16, DM,
                     blockIdx.y * BM, blockIdx.x * BN, DM / BK, 1.f, smem);
    } else {
        // Vt = Wv @ X^T -> [1024, 8192]; tm over DM (bx<8), tn over MTOT (by<64)
        gemm_core<0>(g_Wv16, DM, g_X16, DM, nullptr, g_V16, MTOT,
                     blockIdx.x * BM, blockIdx.y * BN, DM / BK, 1.f, smem);
    }
}

// Causal lower-triangle score tiles: S = (Q K^T)/32
__global__ void __launch_bounds__(128, 2) score_k()
{
    extern __shared__ char smem[];
    int b = blockIdx.z;
    int t = blockIdx.x, ib = 0;
    while ((ib + 1) * (ib + 2) / 2 <= t) ib++;
    int jb = t - ib * (ib + 1) / 2;
    size_t qo = (size_t)b * SEQ * DM;
    gemm_core<1>(g_Q16 + qo, DM, g_K16 + qo, DM,
                 g_S + (size_t)b * SEQ * SEQ, nullptr, SEQ,
                 ib * BM, jb * BN, DM / BK, 0.03125f, smem);
}

// O = P @ V, per-m-tile K limit. Largest-K tiles scheduled FIRST (reverse y).
__global__ void __launch_bounds__(128, 2) pv_k(float* __restrict__ out)
{
    extern __shared__ char smem[];
    int b = blockIdx.z;
    int my = (int)gridDim.y - 1 - (int)blockIdx.y;   // big tiles first
    gemm_core<1>(g_P16 + (size_t)b * SEQ * SEQ, SEQ,
                 g_V16 + (size_t)b * SEQ, MTOT,
                 out + (size_t)b * SEQ * DM, nullptr, DM,
                 my * BM, blockIdx.x * BN,
                 (my + 1) * BM / BK, 1.f, smem);
}

// ------------------------- converts -----------------------------------------
// fp32 -> fp16 (4 elems)
__device__ __forceinline__ void conv4h(const float* in, __half* out, int i) {
    float4 v = *(const float4*)(in + i);
    __half2 a; a.x = __float2half_rn(v.x); a.y = __float2half_rn(v.y);
    __half2 b; b.x = __float2half_rn(v.z); b.y = __float2half_rn(v.w);
    *(__half2*)(out + i)     = a;
    *(__half2*)(out + i + 2) = b;
}
__global__ void convX_k(const float* __restrict__ x) {
    int i = (blockIdx.x * 256 + threadIdx.x) * 4;
    if (i < MTOT * DM) conv4h(x, g_X16, i);
}
__global__ void convW_k(const float* __restrict__ wq,
                        const float* __restrict__ wk,
                        const float* __restrict__ wv) {
    int i = (blockIdx.x * 256 + threadIdx.x) * 4;
    if (i < NW)          conv4h(wq, g_Wq16, i);
    else if (i < 2 * NW) conv4h(wk + (i - NW),     g_Wk16 + (i - NW),     0);
    else if (i < 3 * NW) conv4h(wv + (i - 2 * NW), g_Wv16 + (i - 2 * NW), 0);
}

// ------------------------- causal row softmax -> P fp16 ---------------------
__global__ void __launch_bounds__(256) softmax_k(const float* __restrict__ S,
                                                 __half* __restrict__ P16)
{
    __shared__ float buf[SEQ];
    __shared__ float red[8];
    int row = blockIdx.x;
    int b = row >> 11, i = row & 2047;
    int L = i + 1;
    size_t off = ((size_t)b << 22) + ((size_t)i << 11);
    const float* s = S + off;
    int t = threadIdx.x;

    float m = -3.4e38f;
    for (int j = t; j < L; j += 256) { float v = s[j]; buf[j] = v; m = fmaxf(m, v); }
#pragma unroll
    for (int o = 16; o; o >>= 1) m = fmaxf(m, __shfl_xor_sync(0xffffffffu, m, o));
    if ((t & 31) == 0) red[t >> 5] = m;
    __syncthreads();
    float bm = fmaxf(fmaxf(fmaxf(red[0], red[1]), fmaxf(red[2], red[3])),
                     fmaxf(fmaxf(red[4], red[5]), fmaxf(red[6], red[7])));

    float sum = 0.f;
    for (int j = t; j < L; j += 256) { float p = __expf(buf[j] - bm); buf[j] = p; sum += p; }
#pragma unroll
    for (int o = 16; o; o >>= 1) sum += __shfl_xor_sync(0xffffffffu, sum, o);
    __syncthreads();
    if ((t & 31) == 0) red[t >> 5] = sum;
    __syncthreads();
    float tot = red[0] + red[1] + red[2] + red[3] + red[4] + red[5] + red[6] + red[7];
    float inv = 1.f / tot;

    int Lpad = (L + 127) & ~127;   // zero-fill to tile boundary for PV K-limit
    for (int j = t; j < Lpad; j += 256) {
        float v = (j < L) ? buf[j] * inv : 0.f;
        P16[off + j] = __float2half_rn(v);
    }
}

// ------------------------- host orchestration -------------------------------
extern "C" void kernel_launch(void* const* d_in, const int* in_sizes, int n_in,
                              void* d_out, int out_size)
{
    const float* x  = (const float*)d_in[0];
    const float* Wq = (const float*)d_in[1];
    const float* Wk = (const float*)d_in[2];
    const float* Wv = (const float*)d_in[3];
    float* out = (float*)d_out;

    __half* P16;  float* Sb;
    cudaGetSymbolAddress((void**)&P16, g_P16);
    cudaGetSymbolAddress((void**)&Sb,  g_S);

    cudaFuncSetAttribute(proj_k,  cudaFuncAttributeMaxDynamicSharedMemorySize, SMEM_BYTES);
    cudaFuncSetAttribute(score_k, cudaFuncAttributeMaxDynamicSharedMemorySize, SMEM_BYTES);
    cudaFuncSetAttribute(pv_k,    cudaFuncAttributeMaxDynamicSharedMemorySize, SMEM_BYTES);

    dim3 blk(128);
    convX_k<<<MTOT * DM / 4 / 256, 256>>>(x);                        // launch 0
    convW_k<<<3 * NW / 4 / 256, 256>>>(Wq, Wk, Wv);                  // launch 1
    proj_k<<<dim3(8, 64, 3), blk, SMEM_BYTES>>>();                   // launch 2
    score_k<<<dim3(136, 1, NB), blk, SMEM_BYTES>>>();                // launch 3
    softmax_k<<<MTOT, 256>>>(Sb, P16);                               // launch 4
    pv_k<<<dim3(DM / BN, SEQ / BM, NB), blk, SMEM_BYTES>>>(out);     // launch 5
}

// round 17
// speedup vs baseline: 1.0295x; 1.0295x over previous
#include <cuda_runtime.h>
#include <cuda_fp16.h>
#include <cstdint>

#define NB   4
#define SEQ  2048
#define DM   1024
#define MTOT (NB*SEQ)          // 8192
#define NW   (DM*DM)

#define BM 128
#define BN 128
#define BK 64
#define STAGES 3
#define TILE_BYTES (BM*BK*2)                // 16384 B per operand tile (128B rows)
#define SMEM_BYTES (STAGES*2*TILE_BYTES)    // 98304 B -> 2 CTAs/SM (192KB)

// ------------------------- scratch (__device__ globals; no allocs) ----------
__device__ __half g_X16[MTOT*DM];
__device__ __half g_Wq16[NW];
__device__ __half g_Wk16[NW];
__device__ __half g_Wv16[NW];
__device__ __half g_Q16[MTOT*DM];
__device__ __half g_K16[MTOT*DM];
__device__ __half g_V16[DM*MTOT];            // Vt: [DM, MTOT]
__device__ float  g_S[(size_t)MTOT*SEQ];
__device__ __half g_P16[(size_t)MTOT*SEQ];

// ------------------------- PTX helpers -------------------------------------
__device__ __forceinline__ void cp16(void* s, const void* g) {
    uint32_t sa = (uint32_t)__cvta_generic_to_shared(s);
    asm volatile("cp.async.cg.shared.global [%0], [%1], 16;\n" :: "r"(sa), "l"(g));
}
__device__ __forceinline__ void ldsm4(uint32_t* r, const void* p) {
    uint32_t a = (uint32_t)__cvta_generic_to_shared(p);
    asm volatile("ldmatrix.sync.aligned.m8n8.x4.shared.b16 {%0,%1,%2,%3}, [%4];\n"
                 : "=r"(r[0]), "=r"(r[1]), "=r"(r[2]), "=r"(r[3]) : "r"(a));
}
__device__ __forceinline__ void mma_f16(float* c, const uint32_t* a, const uint32_t* b) {
    asm volatile("mma.sync.aligned.m16n8k16.row.col.f32.f16.f16.f32 "
                 "{%0,%1,%2,%3}, {%4,%5,%6,%7}, {%8,%9}, {%0,%1,%2,%3};\n"
                 : "+f"(c[0]), "+f"(c[1]), "+f"(c[2]), "+f"(c[3])
                 : "r"(a[0]), "r"(a[1]), "r"(a[2]), "r"(a[3]), "r"(b[0]), "r"(b[1]));
}
// 128B rows, 8x16B chunks; chunk' = ch ^ (row&7).
__device__ __forceinline__ int smem_off(int row, int ch) {
    return (row << 7) + (((ch ^ (row & 7)) & 7) << 4);
}

// ------------------------- fp16 single-pass GEMM core (R14 engine) ----------
// D[m][n] = scale * sum_k A[m][k]*B[n][k]  (both K-major fp16)
// OUT 0: fp16 output    OUT 1: fp32 * scale
template<int OUT>
__device__ __forceinline__ void gemm_core(
    const __half* __restrict__ A, int lda,
    const __half* __restrict__ B, int ldb,
    float* __restrict__ Cf, __half* __restrict__ C16, int ldc,
    int tm, int tn, int kIters, float scale, char* smem)
{
    char* sA = smem;
    char* sB = smem + STAGES * TILE_BYTES;

    const int tid  = threadIdx.x;
    const int lane = tid & 31;
    const int warp = tid >> 5;
    const int wm   = warp >> 2;   // 0..1 (64 rows each)
    const int wn   = warp & 3;    // 0..3 (32 cols each)

    auto load_stage = [&](int st, int kOff) {
        char* dA = sA + st * TILE_BYTES;
        char* dB = sB + st * TILE_BYTES;
#pragma unroll
        for (int i = 0; i < 4; i++) {
            int idx = tid + (i << 8);
            int row = idx >> 3, ch = idx & 7;
            int so = smem_off(row, ch);
            cp16(dA + so, A + (size_t)(tm + row) * lda + kOff + (ch << 3));
            cp16(dB + so, B + (size_t)(tn + row) * ldb + kOff + (ch << 3));
        }
    };

    // prologue: prefetch depth 2
#pragma unroll
    for (int s = 0; s < STAGES - 1; s++) {
        if (s < kIters) load_stage(s, s * BK);
        asm volatile("cp.async.commit_group;\n" ::);
    }

    float acc[4][4][4];
#pragma unroll
    for (int a = 0; a < 4; a++)
#pragma unroll
        for (int b = 0; b < 4; b++)
#pragma unroll
            for (int c = 0; c < 4; c++) acc[a][b][c] = 0.f;

    for (int kb = 0; kb < kIters; kb++) {
        asm volatile("cp.async.wait_group 1;\n" ::);   // stage kb resident
        __syncthreads();                                // single sync per iter
        int nk = kb + STAGES - 1;
        if (nk < kIters) load_stage(nk % STAGES, nk * BK);
        asm volatile("cp.async.commit_group;\n" ::);

        int st = kb % STAGES;
        const char* cA = sA + st * TILE_BYTES;
        const char* cB = sB + st * TILE_BYTES;

#pragma unroll
        for (int ks = 0; ks < 4; ks++) {
            // batch all 6 LDSMs up front, then 16 uninterrupted HMMAs
            uint32_t ah[4][4], bh[2][4];
#pragma unroll
            for (int mi = 0; mi < 4; mi++) {
                int r  = wm * 64 + mi * 16 + (lane & 15);
                int ch = ks * 2 + (lane >> 4);
                ldsm4(ah[mi], cA + smem_off(r, ch));
            }
#pragma unroll
            for (int pr = 0; pr < 2; pr++) {
                int r  = wn * 32 + pr * 16 + (lane & 7) + (((lane >> 4) & 1) << 3);
                int ch = ks * 2 + ((lane >> 3) & 1);
                ldsm4(bh[pr], cB + smem_off(r, ch));
            }
#pragma unroll
            for (int pr = 0; pr < 2; pr++) {
                const int n0i = pr * 2;
#pragma unroll
                for (int mi = 0; mi < 4; mi++) {
                    mma_f16(acc[mi][n0i + 0], ah[mi], bh[pr] + 0);
                    mma_f16(acc[mi][n0i + 1], ah[mi], bh[pr] + 2);
                }
            }
        }
    }
    // no trailing sync needed: epilogue touches only registers + gmem

    const int g  = lane >> 2;
    const int tq = lane & 3;
#pragma unroll
    for (int mi = 0; mi < 4; mi++) {
#pragma unroll
        for (int ni = 0; ni < 4; ni++) {
            const float* c = acc[mi][ni];
            int c0 = tn + wn * 32 + ni * 8 + tq * 2;
#pragma unroll
            for (int h = 0; h < 2; h++) {
                int r = tm + wm * 64 + mi * 16 + g + h * 8;
                if (OUT == 0) {
                    __half2 hv;
                    hv.x = __float2half_rn(c[h * 2 + 0]);
                    hv.y = __float2half_rn(c[h * 2 + 1]);
                    *(__half2*)&C16[(size_t)r * ldc + c0] = hv;
                } else {
                    float2 o;
                    o.x = c[h * 2 + 0] * scale;
                    o.y = c[h * 2 + 1] * scale;
                    *(float2*)&Cf[(size_t)r * ldc + c0] = o;
                }
            }
        }
    }
}

// ------------------------- GEMM kernels -------------------------------------
// Merged projections: z=0 Q, z=1 K, z=2 Vt (role-swapped tiles)
__global__ void __launch_bounds__(256, 2) proj_k()
{
    extern __shared__ char smem[];
    int z = blockIdx.z;
    if (z == 0) {
        gemm_core<0>(g_X16, DM, g_Wq16, DM, nullptr, g_Q16, DM,
                     blockIdx.y * BM, blockIdx.x * BN, DM / BK, 1.f, smem);
    } else if (z == 1) {
        gemm_core<0>(g_X16, DM, g_Wk16, DM, nullptr, g_K16, DM,
                     blockIdx.y * BM, blockIdx.x * BN, DM / BK, 1.f, smem);
    } else {
        // Vt = Wv @ X^T -> [1024, 8192]; tm over DM (bx<8), tn over MTOT (by<64)
        gemm_core<0>(g_Wv16, DM, g_X16, DM, nullptr, g_V16, MTOT,
                     blockIdx.x * BM, blockIdx.y * BN, DM / BK, 1.f, smem);
    }
}

// Causal lower-triangle score tiles: S = (Q K^T)/32
__global__ void __launch_bounds__(256, 2) score_k()
{
    extern __shared__ char smem[];
    int b = blockIdx.z;
    int t = blockIdx.x, ib = 0;
    while ((ib + 1) * (ib + 2) / 2 <= t) ib++;
    int jb = t - ib * (ib + 1) / 2;
    size_t qo = (size_t)b * SEQ * DM;
    gemm_core<1>(g_Q16 + qo, DM, g_K16 + qo, DM,
                 g_S + (size_t)b * SEQ * SEQ, nullptr, SEQ,
                 ib * BM, jb * BN, DM / BK, 0.03125f, smem);
}

// O = P @ V, per-m-tile K limit. Largest-K tiles scheduled FIRST (reverse y).
__global__ void __launch_bounds__(256, 2) pv_k(float* __restrict__ out)
{
    extern __shared__ char smem[];
    int b = blockIdx.z;
    int my = (int)gridDim.y - 1 - (int)blockIdx.y;   // big tiles first
    gemm_core<1>(g_P16 + (size_t)b * SEQ * SEQ, SEQ,
                 g_V16 + (size_t)b * SEQ, MTOT,
                 out + (size_t)b * SEQ * DM, nullptr, DM,
                 my * BM, blockIdx.x * BN,
                 (my + 1) * BM / BK, 1.f, smem);
}

// ------------------------- merged convert (X, Wq, Wk, Wv in one launch) -----
__device__ __forceinline__ void conv4h(const float* in, __half* out, int i) {
    float4 v = *(const float4*)(in + i);
    __half2 a; a.x = __float2half_rn(v.x); a.y = __float2half_rn(v.y);
    __half2 b; b.x = __float2half_rn(v.z); b.y = __float2half_rn(v.w);
    *(__half2*)(out + i)     = a;
    *(__half2*)(out + i + 2) = b;
}
#define NX (MTOT*DM)   // 8*NW
__global__ void conv_k(const float* __restrict__ x,
                       const float* __restrict__ wq,
                       const float* __restrict__ wk,
                       const float* __restrict__ wv) {
    int i = (blockIdx.x * 256 + threadIdx.x) * 4;
    if (i < NX)               conv4h(x, g_X16, i);
    else if (i < NX + NW)     conv4h(wq + (i - NX),          g_Wq16 + (i - NX),          0);
    else if (i < NX + 2 * NW) conv4h(wk + (i - NX - NW),     g_Wk16 + (i - NX - NW),     0);
    else if (i < NX + 3 * NW) conv4h(wv + (i - NX - 2 * NW), g_Wv16 + (i - NX - 2 * NW), 0);
}

// ------------------------- causal row softmax -> P fp16 ---------------------
__global__ void __launch_bounds__(256) softmax_k(const float* __restrict__ S,
                                                 __half* __restrict__ P16)
{
    __shared__ float buf[SEQ];
    __shared__ float red[8];
    int row = blockIdx.x;
    int b = row >> 11, i = row & 2047;
    int L = i + 1;
    size_t off = ((size_t)b << 22) + ((size_t)i << 11);
    const float* s = S + off;
    int t = threadIdx.x;

    float m = -3.4e38f;
    for (int j = t; j < L; j += 256) { float v = s[j]; buf[j] = v; m = fmaxf(m, v); }
#pragma unroll
    for (int o = 16; o; o >>= 1) m = fmaxf(m, __shfl_xor_sync(0xffffffffu, m, o));
    if ((t & 31) == 0) red[t >> 5] = m;
    __syncthreads();
    float bm = fmaxf(fmaxf(fmaxf(red[0], red[1]), fmaxf(red[2], red[3])),
                     fmaxf(fmaxf(red[4], red[5]), fmaxf(red[6], red[7])));

    float sum = 0.f;
    for (int j = t; j < L; j += 256) { float p = __expf(buf[j] - bm); buf[j] = p; sum += p; }
#pragma unroll
    for (int o = 16; o; o >>= 1) sum += __shfl_xor_sync(0xffffffffu, sum, o);
    __syncthreads();
    if ((t & 31) == 0) red[t >> 5] = sum;
    __syncthreads();
    float tot = red[0] + red[1] + red[2] + red[3] + red[4] + red[5] + red[6] + red[7];
    float inv = 1.f / tot;

    int Lpad = (L + 127) & ~127;   // zero-fill to tile boundary for PV K-limit
    for (int j = t; j < Lpad; j += 256) {
        float v = (j < L) ? buf[j] * inv : 0.f;
        P16[off + j] = __float2half_rn(v);
    }
}

// ------------------------- host orchestration -------------------------------
extern "C" void kernel_launch(void* const* d_in, const int* in_sizes, int n_in,
                              void* d_out, int out_size)
{
    const float* x  = (const float*)d_in[0];
    const float* Wq = (const float*)d_in[1];
    const float* Wk = (const float*)d_in[2];
    const float* Wv = (const float*)d_in[3];
    float* out = (float*)d_out;

    __half* P16;  float* Sb;
    cudaGetSymbolAddress((void**)&P16, g_P16);
    cudaGetSymbolAddress((void**)&Sb,  g_S);

    cudaFuncSetAttribute(proj_k,  cudaFuncAttributeMaxDynamicSharedMemorySize, SMEM_BYTES);
    cudaFuncSetAttribute(score_k, cudaFuncAttributeMaxDynamicSharedMemorySize, SMEM_BYTES);
    cudaFuncSetAttribute(pv_k,    cudaFuncAttributeMaxDynamicSharedMemorySize, SMEM_BYTES);

    dim3 blk(256);
    conv_k<<<(NX + 3 * NW) / 4 / 256, 256>>>(x, Wq, Wk, Wv);         // launch 0
    proj_k<<<dim3(8, 64, 3), blk, SMEM_BYTES>>>();                   // launch 1
    score_k<<<dim3(136, 1, NB), blk, SMEM_BYTES>>>();                // launch 2
    softmax_k<<<MTOT, 256>>>(Sb, P16);                               // launch 3
    pv_k<<<dim3(DM / BN, SEQ / BM, NB), blk, SMEM_BYTES>>>(out);     // launch 4
}